// round 2
// baseline (speedup 1.0000x reference)
#include <cuda_runtime.h>
#include <cstdint>

// Shapes fixed by the problem: x (64,64,128,128) fp32, coeff (64,32) fp32, out (64,64) fp32.
#define N_ELEM   67108864   // 64*64*128*128
#define N_F4     16777216   // N_ELEM/4
#define N_PLANES 4096       // N*C
#define HW       16384
#define HW4      4096       // HW/4
#define BINS     32

#define MM_GRID  2048       // 2048*256 threads -> exactly 32 iterations over N_F4

// scratch: [0]=encoded min, [1]=encoded max (monotone uint encoding of float)
__device__ unsigned g_mm[2];

__device__ __forceinline__ unsigned fenc(float f) {
    unsigned u = __float_as_uint(f);
    return (u & 0x80000000u) ? ~u : (u | 0x80000000u);
}
__device__ __forceinline__ float fdec(unsigned e) {
    return (e & 0x80000000u) ? __uint_as_float(e ^ 0x80000000u)
                             : __uint_as_float(~e);
}

__global__ void init_kernel() {
    g_mm[0] = 0xFFFFFFFFu;  // running min (encoded): start at +max
    g_mm[1] = 0x00000000u;  // running max (encoded): start at -max
}

__global__ void __launch_bounds__(256) minmax_kernel(const float4* __restrict__ x) {
    float lo =  3.402823466e38f;
    float hi = -3.402823466e38f;
    const int base = blockIdx.x * 256 + threadIdx.x;
    const int stride = MM_GRID * 256;
    #pragma unroll 8
    for (int it = 0; it < N_F4 / stride; it++) {
        float4 v = x[base + it * stride];
        lo = fminf(lo, fminf(fminf(v.x, v.y), fminf(v.z, v.w)));
        hi = fmaxf(hi, fmaxf(fmaxf(v.x, v.y), fmaxf(v.z, v.w)));
    }
    // warp reduce
    #pragma unroll
    for (int o = 16; o; o >>= 1) {
        lo = fminf(lo, __shfl_xor_sync(0xFFFFFFFFu, lo, o));
        hi = fmaxf(hi, __shfl_xor_sync(0xFFFFFFFFu, hi, o));
    }
    __shared__ float s_lo[8], s_hi[8];
    int t = threadIdx.x;
    if ((t & 31) == 0) { s_lo[t >> 5] = lo; s_hi[t >> 5] = hi; }
    __syncthreads();
    if (t < 32) {
        lo = (t < 8) ? s_lo[t] :  3.402823466e38f;
        hi = (t < 8) ? s_hi[t] : -3.402823466e38f;
        #pragma unroll
        for (int o = 4; o; o >>= 1) {
            lo = fminf(lo, __shfl_xor_sync(0xFFFFFFFFu, lo, o));
            hi = fmaxf(hi, __shfl_xor_sync(0xFFFFFFFFu, hi, o));
        }
        if (t == 0) {
            atomicMin(&g_mm[0], fenc(lo));
            atomicMax(&g_mm[1], fenc(hi));
        }
    }
}

__global__ void __launch_bounds__(256) hpool_kernel(const float4* __restrict__ x,
                                                    const float* __restrict__ coeff,
                                                    float* __restrict__ out) {
    __shared__ float s_tau[BINS + 1];
    __shared__ float s_cf[BINS];
    __shared__ float s_red[8];

    // Reverse plane order: pass 1 streamed forward, its tail is L2-resident.
    const int plane = (N_PLANES - 1) - (int)blockIdx.x;
    const int c = plane & 63;

    const float xmin = fdec(g_mm[0]);
    const float xmax = fdec(g_mm[1]);
    // Match jnp.linspace fp32 arithmetic: delta=(stop-start)/div; tau[i]=start + i*delta
    // (separate rn mul + rn add, no fma contraction).
    const float delta     = __fdiv_rn(__fsub_rn(xmax, xmin), 32.0f);
    const float inv_delta = __frcp_rn(delta);
    const float nbase     = -xmin * inv_delta;  // f = fma(x, inv_delta, nbase), err << 1 bin

    const int t = threadIdx.x;
    if (t <= BINS) s_tau[t] = __fadd_rn(xmin, __fmul_rn((float)t, delta));
    if (t < BINS)  s_cf[t]  = coeff[c * BINS + t];
    __syncthreads();

    const float4* __restrict__ px = x + (size_t)plane * HW4;
    float acc = 0.0f;

    #pragma unroll 4
    for (int it = 0; it < HW4 / 256; it++) {
        float4 v = px[t + it * 256];
        float vv[4] = {v.x, v.y, v.z, v.w};
        #pragma unroll
        for (int j = 0; j < 4; j++) {
            const float xv = vv[j];
            // approximate bin, then exact correction against tau (== searchsorted right - 1)
            float f = fminf(fmaf(xv, inv_delta, nbase), 31.0f);
            int i0 = (int)f;                 // trunc-toward-zero clamps tiny negatives to 0
            const bool up = (i0 < BINS - 1) && (xv >= s_tau[i0 + 1]);
            const bool dn = (i0 > 0)        && (xv <  s_tau[i0]);
            i0 += (int)up - (int)dn;
            // tanh(x) = 1 - 2/(exp2(2x*log2e)+1)  (2 MUFU + 3 FMA, ~few-ulp accurate)
            float e, r;
            asm("ex2.approx.f32 %0, %1;" : "=f"(e) : "f"(xv * 2.88539004f));
            asm("rcp.approx.f32 %0, %1;" : "=f"(r) : "f"(e + 1.0f));
            const float th = fmaf(-2.0f, r, 1.0f);
            acc = fmaf(th, s_cf[i0], acc);
        }
    }

    // block reduce (8 warps)
    #pragma unroll
    for (int o = 16; o; o >>= 1) acc += __shfl_xor_sync(0xFFFFFFFFu, acc, o);
    if ((t & 31) == 0) s_red[t >> 5] = acc;
    __syncthreads();
    if (t < 32) {
        float a = (t < 8) ? s_red[t] : 0.0f;
        #pragma unroll
        for (int o = 4; o; o >>= 1) a += __shfl_xor_sync(0xFFFFFFFFu, a, o);
        if (t == 0) out[plane] = a;
    }
}

extern "C" void kernel_launch(void* const* d_in, const int* in_sizes, int n_in,
                              void* d_out, int out_size) {
    const float4* x     = (const float4*)d_in[0];
    const float*  coeff = (const float*)d_in[1];
    float*        out   = (float*)d_out;

    init_kernel<<<1, 1>>>();
    minmax_kernel<<<MM_GRID, 256>>>(x);
    hpool_kernel<<<N_PLANES, 256>>>(x, coeff, out);
}

// round 3
// speedup vs baseline: 1.2116x; 1.2116x over previous
#include <cuda_runtime.h>
#include <cstdint>

// Shapes fixed by the problem: x (64,64,128,128) fp32, coeff (64,32) fp32, out (64,64) fp32.
#define N_ELEM   67108864   // 64*64*128*128
#define N_F4     16777216   // N_ELEM/4
#define N_PLANES 4096       // N*C
#define HW4      4096       // 128*128/4
#define BINS     32
#define MM_GRID  1184       // 148 SMs * 8 blocks: exactly one full wave
#define MARGIN   0.001f     // bin-fraction safety margin (true error < ~3e-5)

// per-block min/max partials (written fresh every launch -> no init kernel, no atomics)
__device__ float2 g_partials[MM_GRID];

__global__ void __launch_bounds__(256) minmax_kernel(const float4* __restrict__ x) {
    float lo =  3.402823466e38f;
    float hi = -3.402823466e38f;
    const int base   = blockIdx.x * 256 + threadIdx.x;
    const int stride = MM_GRID * 256;
    #pragma unroll 8
    for (int i = base; i < N_F4; i += stride) {
        float4 v = x[i];
        lo = fminf(lo, fminf(fminf(v.x, v.y), fminf(v.z, v.w)));
        hi = fmaxf(hi, fmaxf(fmaxf(v.x, v.y), fmaxf(v.z, v.w)));
    }
    #pragma unroll
    for (int o = 16; o; o >>= 1) {
        lo = fminf(lo, __shfl_xor_sync(0xFFFFFFFFu, lo, o));
        hi = fmaxf(hi, __shfl_xor_sync(0xFFFFFFFFu, hi, o));
    }
    __shared__ float s_lo[8], s_hi[8];
    const int t = threadIdx.x;
    if ((t & 31) == 0) { s_lo[t >> 5] = lo; s_hi[t >> 5] = hi; }
    __syncthreads();
    if (t < 32) {
        lo = (t < 8) ? s_lo[t] :  3.402823466e38f;
        hi = (t < 8) ? s_hi[t] : -3.402823466e38f;
        #pragma unroll
        for (int o = 4; o; o >>= 1) {
            lo = fminf(lo, __shfl_xor_sync(0xFFFFFFFFu, lo, o));
            hi = fmaxf(hi, __shfl_xor_sync(0xFFFFFFFFu, hi, o));
        }
        if (t == 0) g_partials[blockIdx.x] = make_float2(lo, hi);
    }
}

__global__ void __launch_bounds__(256) hpool_kernel(const float4* __restrict__ x,
                                                    const float* __restrict__ coeff,
                                                    float* __restrict__ out) {
    __shared__ float s_red[8];
    __shared__ float s_mm[2];

    const int t = threadIdx.x;

    // ---- prologue: reduce per-block minmax partials (deterministic, L2-resident) ----
    {
        float lo =  3.402823466e38f;
        float hi = -3.402823466e38f;
        #pragma unroll
        for (int i = t; i < MM_GRID; i += 256) {
            float2 p = g_partials[i];
            lo = fminf(lo, p.x);
            hi = fmaxf(hi, p.y);
        }
        #pragma unroll
        for (int o = 16; o; o >>= 1) {
            lo = fminf(lo, __shfl_xor_sync(0xFFFFFFFFu, lo, o));
            hi = fmaxf(hi, __shfl_xor_sync(0xFFFFFFFFu, hi, o));
        }
        if ((t & 31) == 0) { s_red[(t >> 5)] = lo; }
        __syncthreads();
        if (t < 32) {
            float a = (t < 8) ? s_red[t] : 3.402823466e38f;
            #pragma unroll
            for (int o = 4; o; o >>= 1) a = fminf(a, __shfl_xor_sync(0xFFFFFFFFu, a, o));
            if (t == 0) s_mm[0] = a;
        }
        __syncthreads();
        if ((t & 31) == 0) { s_red[(t >> 5)] = hi; }
        __syncthreads();
        if (t < 32) {
            float a = (t < 8) ? s_red[t] : -3.402823466e38f;
            #pragma unroll
            for (int o = 4; o; o >>= 1) a = fmaxf(a, __shfl_xor_sync(0xFFFFFFFFu, a, o));
            if (t == 0) s_mm[1] = a;
        }
        __syncthreads();
    }

    const float xmin = s_mm[0];
    const float xmax = s_mm[1];
    // jnp.linspace fp32 semantics: delta=(stop-start)/32; tau[i]=rn(start + rn(i*delta))
    const float delta     = __fdiv_rn(__fsub_rn(xmax, xmin), 32.0f);
    const float inv_delta = __frcp_rn(delta);
    const float nbase     = -xmin * inv_delta;

    // Reverse plane order: minmax streamed forward, its tail is L2-resident.
    const int plane = (N_PLANES - 1) - (int)blockIdx.x;
    const int c = plane & 63;

    // lane l holds coeff[c][l]; gather later via shfl (BINS == warp size)
    const float cf_lane = coeff[c * BINS + (t & 31)];

    const float4* __restrict__ px = x + (size_t)plane * HW4;
    float acc = 0.0f;

    #pragma unroll 4
    for (int it = 0; it < HW4 / 256; it++) {
        float4 v = px[t + it * 256];
        float vv[4] = {v.x, v.y, v.z, v.w};
        #pragma unroll
        for (int j = 0; j < 4; j++) {
            const float xv = vv[j];
            // approximate bin index; exact unless within MARGIN of a boundary
            const float f = fminf(fmaf(xv, inv_delta, nbase), 31.0f);
            int i0 = (int)f;                       // trunc clamps tiny negatives to 0
            if (fabsf(f - rintf(f)) < MARGIN) {    // rare (~0.2% of lanes): exact fix-up
                const float tup = __fadd_rn(xmin, __fmul_rn((float)(i0 + 1), delta));
                if (i0 < BINS - 1 && xv >= tup) {
                    i0++;
                } else {
                    const float tlo = __fadd_rn(xmin, __fmul_rn((float)i0, delta));
                    if (i0 > 0 && xv < tlo) i0--;
                }
            }
            // tanh(x) = 1 - 2/(exp2(2x*log2e)+1)  (2 MUFU + 3 FMA, few-ulp accurate)
            float e, r;
            asm("ex2.approx.f32 %0, %1;" : "=f"(e) : "f"(xv * 2.88539004f));
            asm("rcp.approx.f32 %0, %1;" : "=f"(r) : "f"(e + 1.0f));
            const float th = fmaf(-2.0f, r, 1.0f);
            const float cf = __shfl_sync(0xFFFFFFFFu, cf_lane, i0);
            acc = fmaf(th, cf, acc);
        }
    }

    // block reduce (8 warps)
    #pragma unroll
    for (int o = 16; o; o >>= 1) acc += __shfl_xor_sync(0xFFFFFFFFu, acc, o);
    __syncthreads();  // s_red reuse
    if ((t & 31) == 0) s_red[t >> 5] = acc;
    __syncthreads();
    if (t < 32) {
        float a = (t < 8) ? s_red[t] : 0.0f;
        #pragma unroll
        for (int o = 4; o; o >>= 1) a += __shfl_xor_sync(0xFFFFFFFFu, a, o);
        if (t == 0) out[plane] = a;
    }
}

extern "C" void kernel_launch(void* const* d_in, const int* in_sizes, int n_in,
                              void* d_out, int out_size) {
    const float4* x     = (const float4*)d_in[0];
    const float*  coeff = (const float*)d_in[1];
    float*        out   = (float*)d_out;

    minmax_kernel<<<MM_GRID, 256>>>(x);
    hpool_kernel<<<N_PLANES, 256>>>(x, coeff, out);
}

// round 5
// speedup vs baseline: 1.3520x; 1.1159x over previous
#include <cuda_runtime.h>
#include <cstdint>

// Shapes fixed by the problem: x (64,64,128,128) fp32, coeff (64,32) fp32, out (64,64) fp32.
#define N_ELEM   67108864   // 64*64*128*128
#define N_F4     16777216   // N_ELEM/4
#define N_PLANES 4096       // N*C
#define HW4      4096       // 128*128/4
#define BINS     32
#define MM_GRID  1184       // 148 SMs * 8 blocks: exactly one full wave
#define MARGIN   0.001f     // bin-fraction safety margin (true error < ~3e-5)

// per-block min/max partials (written fresh every launch -> no init kernel, no atomics)
__device__ float2 g_partials[MM_GRID];

__global__ void __launch_bounds__(256) minmax_kernel(const float4* __restrict__ x) {
    float lo =  3.402823466e38f;
    float hi = -3.402823466e38f;
    const int base   = blockIdx.x * 256 + threadIdx.x;
    const int stride = MM_GRID * 256;
    #pragma unroll 8
    for (int i = base; i < N_F4; i += stride) {
        float4 v = x[i];
        lo = fminf(lo, fminf(fminf(v.x, v.y), fminf(v.z, v.w)));
        hi = fmaxf(hi, fmaxf(fmaxf(v.x, v.y), fmaxf(v.z, v.w)));
    }
    #pragma unroll
    for (int o = 16; o; o >>= 1) {
        lo = fminf(lo, __shfl_xor_sync(0xFFFFFFFFu, lo, o));
        hi = fmaxf(hi, __shfl_xor_sync(0xFFFFFFFFu, hi, o));
    }
    __shared__ float s_lo[8], s_hi[8];
    const int t = threadIdx.x;
    if ((t & 31) == 0) { s_lo[t >> 5] = lo; s_hi[t >> 5] = hi; }
    __syncthreads();
    if (t < 32) {
        lo = (t < 8) ? s_lo[t] :  3.402823466e38f;
        hi = (t < 8) ? s_hi[t] : -3.402823466e38f;
        #pragma unroll
        for (int o = 4; o; o >>= 1) {
            lo = fminf(lo, __shfl_xor_sync(0xFFFFFFFFu, lo, o));
            hi = fmaxf(hi, __shfl_xor_sync(0xFFFFFFFFu, hi, o));
        }
        if (t == 0) g_partials[blockIdx.x] = make_float2(lo, hi);
    }
}

__global__ void __launch_bounds__(256) hpool_kernel(const float4* __restrict__ x,
                                                    const float* __restrict__ coeff,
                                                    float* __restrict__ out) {
    __shared__ float s_red[8];
    __shared__ float s_mm[2];

    const int t = threadIdx.x;

    // ---- prologue: reduce per-block minmax partials (deterministic, L2-resident) ----
    {
        float lo =  3.402823466e38f;
        float hi = -3.402823466e38f;
        #pragma unroll
        for (int i = t; i < MM_GRID; i += 256) {
            float2 p = g_partials[i];
            lo = fminf(lo, p.x);
            hi = fmaxf(hi, p.y);
        }
        #pragma unroll
        for (int o = 16; o; o >>= 1) {
            lo = fminf(lo, __shfl_xor_sync(0xFFFFFFFFu, lo, o));
            hi = fmaxf(hi, __shfl_xor_sync(0xFFFFFFFFu, hi, o));
        }
        if ((t & 31) == 0) { s_red[(t >> 5)] = lo; }
        __syncthreads();
        if (t < 32) {
            float a = (t < 8) ? s_red[t] : 3.402823466e38f;
            #pragma unroll
            for (int o = 4; o; o >>= 1) a = fminf(a, __shfl_xor_sync(0xFFFFFFFFu, a, o));
            if (t == 0) s_mm[0] = a;
        }
        __syncthreads();
        if ((t & 31) == 0) { s_red[(t >> 5)] = hi; }
        __syncthreads();
        if (t < 32) {
            float a = (t < 8) ? s_red[t] : -3.402823466e38f;
            #pragma unroll
            for (int o = 4; o; o >>= 1) a = fmaxf(a, __shfl_xor_sync(0xFFFFFFFFu, a, o));
            if (t == 0) s_mm[1] = a;
        }
        __syncthreads();
    }

    const float xmin = s_mm[0];
    const float xmax = s_mm[1];
    // jnp.linspace fp32 semantics: delta=(stop-start)/32; tau[i]=rn(start + rn(i*delta))
    const float delta     = __fdiv_rn(__fsub_rn(xmax, xmin), 32.0f);
    const float inv_delta = __frcp_rn(delta);
    const float nbase     = -xmin * inv_delta;

    // Reverse plane order: minmax streamed forward, its tail is L2-resident
    // (and this leaves the FRONT of x in L2 for the next graph replay's minmax).
    const int plane = (N_PLANES - 1) - (int)blockIdx.x;
    const int c = plane & 63;

    // lane l holds coeff[c][l]; gather via shfl (BINS == warp size)
    const float cf_lane = coeff[c * BINS + (t & 31)];

    const float4* __restrict__ px = x + (size_t)plane * HW4;
    float acc = 0.0f;

    #pragma unroll 4
    for (int it = 0; it < HW4 / 256; it++) {
        float4 v = px[t + it * 256];
        float vv[4] = {v.x, v.y, v.z, v.w};
        #pragma unroll
        for (int j = 0; j < 4; j++) {
            const float xv = vv[j];
            // approximate bin index; exact unless within MARGIN of a boundary
            const float f = fmaf(xv, inv_delta, nbase);
            int i0 = (int)fminf(f, 31.0f);         // trunc clamps tiny negatives to 0
            const float r = rintf(f);
            if (fabsf(f - r) < MARGIN) {           // rare: exact linspace fix-up
                const int ir = (int)r;
                // boundary in question is tau[ir] = rn(xmin + rn(ir*delta))
                const float tau_r = __fadd_rn(xmin, __fmul_rn((float)ir, delta));
                i0 = (xv >= tau_r) ? ir : ir - 1;
                i0 = min(max(i0, 0), BINS - 1);
            }
            // hardware tanh (1 MUFU op)
            float th;
            asm("tanh.approx.f32 %0, %1;" : "=f"(th) : "f"(xv));
            const float cf = __shfl_sync(0xFFFFFFFFu, cf_lane, i0);
            acc = fmaf(th, cf, acc);
        }
    }

    // block reduce (8 warps)
    #pragma unroll
    for (int o = 16; o; o >>= 1) acc += __shfl_xor_sync(0xFFFFFFFFu, acc, o);
    __syncthreads();  // s_red reuse
    if ((t & 31) == 0) s_red[t >> 5] = acc;
    __syncthreads();
    if (t < 32) {
        float a = (t < 8) ? s_red[t] : 0.0f;
        #pragma unroll
        for (int o = 4; o; o >>= 1) a += __shfl_xor_sync(0xFFFFFFFFu, a, o);
        if (t == 0) out[plane] = a;
    }
}

extern "C" void kernel_launch(void* const* d_in, const int* in_sizes, int n_in,
                              void* d_out, int out_size) {
    const float4* x     = (const float4*)d_in[0];
    const float*  coeff = (const float*)d_in[1];
    float*        out   = (float*)d_out;

    minmax_kernel<<<MM_GRID, 256>>>(x);
    hpool_kernel<<<N_PLANES, 256>>>(x, coeff, out);
}

// round 6
// speedup vs baseline: 1.3555x; 1.0026x over previous
#include <cuda_runtime.h>
#include <cstdint>

// Shapes fixed by the problem: x (64,64,128,128) fp32, coeff (64,32) fp32, out (64,64) fp32.
#define N_ELEM   67108864   // 64*64*128*128
#define N_F4     16777216   // N_ELEM/4
#define N_PLANES 4096       // N*C
#define HW4      4096       // 128*128/4
#define BINS     32
#define MM_GRID  1184       // 148 SMs * 8 blocks: exactly one full wave
#define MARGIN   0.001f     // bin-fraction safety margin (true error < ~3e-5)

// per-block min/max partials (written fresh every launch -> no init kernel, no atomics)
__device__ float2 g_partials[MM_GRID];

__global__ void __launch_bounds__(256) minmax_kernel(const float4* __restrict__ x) {
    float lo =  3.402823466e38f;
    float hi = -3.402823466e38f;
    const int base   = blockIdx.x * 256 + threadIdx.x;
    const int stride = MM_GRID * 256;
    #pragma unroll 8
    for (int i = base; i < N_F4; i += stride) {
        float4 v = x[i];
        lo = fminf(lo, fminf(fminf(v.x, v.y), fminf(v.z, v.w)));
        hi = fmaxf(hi, fmaxf(fmaxf(v.x, v.y), fmaxf(v.z, v.w)));
    }
    #pragma unroll
    for (int o = 16; o; o >>= 1) {
        lo = fminf(lo, __shfl_xor_sync(0xFFFFFFFFu, lo, o));
        hi = fmaxf(hi, __shfl_xor_sync(0xFFFFFFFFu, hi, o));
    }
    __shared__ float s_lo[8], s_hi[8];
    const int t = threadIdx.x;
    if ((t & 31) == 0) { s_lo[t >> 5] = lo; s_hi[t >> 5] = hi; }
    __syncthreads();
    if (t < 32) {
        lo = (t < 8) ? s_lo[t] :  3.402823466e38f;
        hi = (t < 8) ? s_hi[t] : -3.402823466e38f;
        #pragma unroll
        for (int o = 4; o; o >>= 1) {
            lo = fminf(lo, __shfl_xor_sync(0xFFFFFFFFu, lo, o));
            hi = fmaxf(hi, __shfl_xor_sync(0xFFFFFFFFu, hi, o));
        }
        if (t == 0) g_partials[blockIdx.x] = make_float2(lo, hi);
    }
}

__global__ void __launch_bounds__(256) hpool_kernel(const float4* __restrict__ x,
                                                    const float* __restrict__ coeff,
                                                    float* __restrict__ out) {
    __shared__ float s_red[8];
    __shared__ float s_mm[2];

    const int t = threadIdx.x;

    // ---- prologue: reduce per-block minmax partials (deterministic, L2-resident) ----
    {
        float lo =  3.402823466e38f;
        float hi = -3.402823466e38f;
        #pragma unroll
        for (int i = t; i < MM_GRID; i += 256) {
            float2 p = g_partials[i];
            lo = fminf(lo, p.x);
            hi = fmaxf(hi, p.y);
        }
        #pragma unroll
        for (int o = 16; o; o >>= 1) {
            lo = fminf(lo, __shfl_xor_sync(0xFFFFFFFFu, lo, o));
            hi = fmaxf(hi, __shfl_xor_sync(0xFFFFFFFFu, hi, o));
        }
        if ((t & 31) == 0) { s_red[(t >> 5)] = lo; }
        __syncthreads();
        if (t < 32) {
            float a = (t < 8) ? s_red[t] : 3.402823466e38f;
            #pragma unroll
            for (int o = 4; o; o >>= 1) a = fminf(a, __shfl_xor_sync(0xFFFFFFFFu, a, o));
            if (t == 0) s_mm[0] = a;
        }
        __syncthreads();
        if ((t & 31) == 0) { s_red[(t >> 5)] = hi; }
        __syncthreads();
        if (t < 32) {
            float a = (t < 8) ? s_red[t] : -3.402823466e38f;
            #pragma unroll
            for (int o = 4; o; o >>= 1) a = fmaxf(a, __shfl_xor_sync(0xFFFFFFFFu, a, o));
            if (t == 0) s_mm[1] = a;
        }
        __syncthreads();
    }

    const float xmin = s_mm[0];
    const float xmax = s_mm[1];
    // jnp.linspace fp32 semantics: delta=(stop-start)/32; tau[i]=rn(start + rn(i*delta))
    const float delta     = __fdiv_rn(__fsub_rn(xmax, xmin), 32.0f);
    const float inv_delta = __frcp_rn(delta);
    const float nbase     = -xmin * inv_delta;

    // Reverse plane order: minmax streamed forward, its tail is L2-resident
    // (and this leaves the FRONT of x in L2 for the next graph replay's minmax).
    const int plane = (N_PLANES - 1) - (int)blockIdx.x;
    const int c = plane & 63;

    // lane l holds coeff[c][l]; gather via shfl (BINS == warp size)
    const float cf_lane = coeff[c * BINS + (t & 31)];

    const float4* __restrict__ p = x + (size_t)plane * HW4 + t;
    float acc = 0.0f;

    // software pipeline: 2 chunks x 4 float4 in flight (8 outstanding LDG.128/thread)
    float4 b0 = p[0], b1 = p[256], b2 = p[512], b3 = p[768];

    #pragma unroll
    for (int ch = 0; ch < 4; ch++) {
        float4 n0, n1, n2, n3;
        if (ch < 3) {
            const float4* q = p + (ch + 1) * 1024;
            n0 = q[0]; n1 = q[256]; n2 = q[512]; n3 = q[768];
        }
        const float vv[16] = {b0.x, b0.y, b0.z, b0.w,  b1.x, b1.y, b1.z, b1.w,
                              b2.x, b2.y, b2.z, b2.w,  b3.x, b3.y, b3.z, b3.w};
        #pragma unroll
        for (int j = 0; j < 16; j++) {
            const float xv = vv[j];
            // approximate bin index; exact unless within MARGIN of a boundary.
            // No clamp needed: f>=32 or f<0 only happens inside the MARGIN window,
            // where the fixup path clamps.
            const float f = fmaf(xv, inv_delta, nbase);
            int i0 = (int)f;                       // trunc clamps tiny negatives to 0
            const float r = rintf(f);
            if (fabsf(f - r) < MARGIN) {           // rare: exact linspace fix-up
                const int ir = (int)r;
                const float tau_r = __fadd_rn(xmin, __fmul_rn((float)ir, delta));
                i0 = (xv >= tau_r) ? ir : ir - 1;
                i0 = min(max(i0, 0), BINS - 1);
            }
            float th;
            asm("tanh.approx.f32 %0, %1;" : "=f"(th) : "f"(xv));
            const float cf = __shfl_sync(0xFFFFFFFFu, cf_lane, i0);
            acc = fmaf(th, cf, acc);
        }
        b0 = n0; b1 = n1; b2 = n2; b3 = n3;
    }

    // block reduce (8 warps)
    #pragma unroll
    for (int o = 16; o; o >>= 1) acc += __shfl_xor_sync(0xFFFFFFFFu, acc, o);
    __syncthreads();  // s_red reuse
    if ((t & 31) == 0) s_red[t >> 5] = acc;
    __syncthreads();
    if (t < 32) {
        float a = (t < 8) ? s_red[t] : 0.0f;
        #pragma unroll
        for (int o = 4; o; o >>= 1) a += __shfl_xor_sync(0xFFFFFFFFu, a, o);
        if (t == 0) out[plane] = a;
    }
}

extern "C" void kernel_launch(void* const* d_in, const int* in_sizes, int n_in,
                              void* d_out, int out_size) {
    const float4* x     = (const float4*)d_in[0];
    const float*  coeff = (const float*)d_in[1];
    float*        out   = (float*)d_out;

    minmax_kernel<<<MM_GRID, 256>>>(x);
    hpool_kernel<<<N_PLANES, 256>>>(x, coeff, out);
}